// round 1
// baseline (speedup 1.0000x reference)
#include <cuda_runtime.h>
#include <math.h>

#define Nn   100000
#define Ee   1600000
#define ETOT (Ee + Nn)
#define DINq 16
#define Hq   128
#define HEADSq 4
#define DOUTq  32
#define Gq   64
#define FOUTq 256

// ---- scratch (static device memory; no allocations allowed) ----
__device__ float g_h[(size_t)Nn * Hq];       // node features (current layer input / output)
__device__ float g_hp[(size_t)Nn * Hq];      // h @ Wg
__device__ float g_agg[(size_t)Nn * Hq];     // aggregation accumulator
__device__ float g_alS[Nn * HEADSq];
__device__ float g_alD[Nn * HEADSq];
__device__ float g_m[Nn * HEADSq];           // segment max
__device__ float g_den[Nn * HEADSq];         // segment sum of exp
__device__ float g_ebuf[(size_t)ETOT * HEADSq];  // per-edge logit, then exp
__device__ float g_psum[Gq * Hq];
__device__ float g_pmax[Gq * Hq];
__device__ float g_cnt[Gq];

__device__ __forceinline__ void atomicMaxFloat(float* addr, float v) {
    if (v >= 0.0f) atomicMax((int*)addr, __float_as_int(v));
    else           atomicMin((unsigned int*)addr, __float_as_uint(v));
}

__device__ __forceinline__ float gelu_exact(float v) {
    return 0.5f * v * (1.0f + erff(v * 0.70710678118654752f));
}

// ---------------- tiled GEMM: C[M x 128] = A[M x K] @ W[K x 128] ----------------
template<int K, bool DO_GELU, bool DO_BIAS>
__global__ void gemm128(const float* __restrict__ A, const float* __restrict__ W,
                        const float* __restrict__ bias, float* __restrict__ C, int M)
{
    const int BN = 64, BK = 16;
    __shared__ float As[BK][BN + 4];   // stride 68 floats (16B-aligned rows)
    __shared__ float Ws[BK][Hq];
    int tid = threadIdx.x;            // 256 threads
    int m0  = blockIdx.x * BN;
    int c0  = (tid & 31) * 4;
    int r0  = (tid >> 5) * 8;

    float acc[8][4];
#pragma unroll
    for (int r = 0; r < 8; r++)
#pragma unroll
        for (int q = 0; q < 4; q++) acc[r][q] = 0.f;

    for (int k0 = 0; k0 < K; k0 += BK) {
        for (int i = tid; i < BN * BK; i += 256) {
            int r = i / BK, k = i % BK;
            As[k][r] = (m0 + r < M) ? A[(size_t)(m0 + r) * K + k0 + k] : 0.f;
        }
        for (int i = tid; i < BK * Hq; i += 256) {
            int k = i / Hq, c = i % Hq;
            Ws[k][c] = W[(size_t)(k0 + k) * Hq + c];
        }
        __syncthreads();
#pragma unroll
        for (int kk = 0; kk < BK; kk++) {
            float4 w  = *(const float4*)&Ws[kk][c0];
            float4 a0 = *(const float4*)&As[kk][r0];
            float4 a1 = *(const float4*)&As[kk][r0 + 4];
            float av[8] = {a0.x, a0.y, a0.z, a0.w, a1.x, a1.y, a1.z, a1.w};
#pragma unroll
            for (int r = 0; r < 8; r++) {
                acc[r][0] += av[r] * w.x;
                acc[r][1] += av[r] * w.y;
                acc[r][2] += av[r] * w.z;
                acc[r][3] += av[r] * w.w;
            }
        }
        __syncthreads();
    }

#pragma unroll
    for (int r = 0; r < 8; r++) {
        int m = m0 + r0 + r;
        if (m < M) {
            float4 o;
            float* po = &o.x;
#pragma unroll
            for (int q = 0; q < 4; q++) {
                float v = acc[r][q];
                if (DO_BIAS) v += bias[c0 + q];
                if (DO_GELU) v = gelu_exact(v);
                po[q] = v;
            }
            *(float4*)&C[(size_t)m * Hq + c0] = o;
        }
    }
}

// ---------------- attention logits per node/head ----------------
__global__ void attn_logits(const float* __restrict__ a_s, const float* __restrict__ a_d)
{
    int idx = blockIdx.x * blockDim.x + threadIdx.x;   // n*4 + head
    if (idx >= Nn * HEADSq) return;
    int n = idx >> 2, hd = idx & 3;
    const float* hrow = g_hp + (size_t)n * Hq + hd * DOUTq;
    const float* asr  = a_s + hd * DOUTq;
    const float* adr  = a_d + hd * DOUTq;
    float s1 = 0.f, s2 = 0.f;
#pragma unroll
    for (int d = 0; d < DOUTq; d += 4) {
        float4 v = *(const float4*)&hrow[d];
        float4 a = *(const float4*)&asr[d];
        float4 b = *(const float4*)&adr[d];
        s1 += v.x * a.x + v.y * a.y + v.z * a.z + v.w * a.w;
        s2 += v.x * b.x + v.y * b.y + v.z * b.z + v.w * b.w;
    }
    g_alS[idx] = s1;
    g_alD[idx] = s2;
}

// ---------------- per-layer clears ----------------
__global__ void clear_layer()
{
    int idx = blockIdx.x * blockDim.x + threadIdx.x;
    if (idx < Nn * Hq) g_agg[idx] = 0.f;
    if (idx < Nn * HEADSq) { g_m[idx] = -INFINITY; g_den[idx] = 0.f; }
}

// ---------------- edge pass A: logits + segment max ----------------
__global__ void edge_max(const int* __restrict__ ei)
{
    int gid = blockIdx.x * blockDim.x + threadIdx.x;
    if (gid >= ETOT * HEADSq) return;
    int e = gid >> 2, hd = gid & 3;
    int s, d;
    if (e < Ee) { s = ei[e]; d = ei[Ee + e]; } else { s = d = e - Ee; }
    float l = g_alS[s * HEADSq + hd] + g_alD[d * HEADSq + hd];
    l = (l > 0.f) ? l : 0.2f * l;
    g_ebuf[gid] = l;
    atomicMaxFloat(&g_m[d * HEADSq + hd], l);
}

// ---------------- edge pass B: exp + segment sum ----------------
__global__ void edge_exp(const int* __restrict__ ei)
{
    int gid = blockIdx.x * blockDim.x + threadIdx.x;
    if (gid >= ETOT * HEADSq) return;
    int e = gid >> 2, hd = gid & 3;
    int d = (e < Ee) ? ei[Ee + e] : (e - Ee);
    float ex = expf(g_ebuf[gid] - g_m[d * HEADSq + hd]);
    g_ebuf[gid] = ex;
    atomicAdd(&g_den[d * HEADSq + hd], ex);
}

// ---------------- edge pass C: weighted scatter (warp per edge) ----------------
__global__ void edge_scatter(const int* __restrict__ ei)
{
    int t = blockIdx.x * blockDim.x + threadIdx.x;
    int e = t >> 5;
    if (e >= ETOT) return;
    int lane = t & 31;
    int s, d;
    if (e < Ee) { s = ei[e]; d = ei[Ee + e]; } else { s = d = e - Ee; }
    int hd = lane >> 3;   // dims lane*4..lane*4+3 belong to head lane/8
    float alpha = g_ebuf[(size_t)e * HEADSq + hd] / (g_den[d * HEADSq + hd] + 1e-16f);
    float4 v = *(const float4*)&g_hp[(size_t)s * Hq + lane * 4];
    float* o = &g_agg[(size_t)d * Hq + lane * 4];
    atomicAdd(o + 0, v.x * alpha);
    atomicAdd(o + 1, v.y * alpha);
    atomicAdd(o + 2, v.z * alpha);
    atomicAdd(o + 3, v.w * alpha);
}

// ---------------- bias + residual + layernorm (warp per node) ----------------
__global__ void post_ln(const float* __restrict__ bg, const float* __restrict__ ga,
                        const float* __restrict__ be)
{
    int t = blockIdx.x * blockDim.x + threadIdx.x;
    int n = t >> 5;
    if (n >= Nn) return;
    int lane = t & 31;
    size_t base = (size_t)n * Hq + lane * 4;
    float4 a  = *(const float4*)&g_agg[base];
    float4 hv = *(const float4*)&g_h[base];
    float4 b4 = *(const float4*)&bg[lane * 4];
    float v0 = a.x + b4.x + hv.x;
    float v1 = a.y + b4.y + hv.y;
    float v2 = a.z + b4.z + hv.z;
    float v3 = a.w + b4.w + hv.w;

    float s = v0 + v1 + v2 + v3;
#pragma unroll
    for (int o = 16; o; o >>= 1) s += __shfl_xor_sync(0xffffffffu, s, o);
    float mu = s * (1.0f / 128.0f);
    float d0 = v0 - mu, d1 = v1 - mu, d2 = v2 - mu, d3 = v3 - mu;
    float q = d0 * d0 + d1 * d1 + d2 * d2 + d3 * d3;
#pragma unroll
    for (int o = 16; o; o >>= 1) q += __shfl_xor_sync(0xffffffffu, q, o);
    float rs = rsqrtf(q * (1.0f / 128.0f) + 1e-5f);

    float4 g4 = *(const float4*)&ga[lane * 4];
    float4 e4 = *(const float4*)&be[lane * 4];
    float4 outv;
    outv.x = d0 * rs * g4.x + e4.x;
    outv.y = d1 * rs * g4.y + e4.y;
    outv.z = d2 * rs * g4.z + e4.z;
    outv.w = d3 * rs * g4.w + e4.w;
    *(float4*)&g_h[base] = outv;
}

// ---------------- pooling ----------------
__global__ void pool_clear()
{
    int idx = blockIdx.x * blockDim.x + threadIdx.x;
    if (idx < Gq * Hq) { g_psum[idx] = 0.f; g_pmax[idx] = -INFINITY; }
    if (idx < Gq) g_cnt[idx] = 0.f;
}

__global__ void pool_scatter(const int* __restrict__ n2g)
{
    int t = blockIdx.x * blockDim.x + threadIdx.x;
    int n = t >> 5;
    if (n >= Nn) return;
    int lane = t & 31;
    int g = n2g[n];
    if (lane == 0) atomicAdd(&g_cnt[g], 1.0f);
    float4 v = *(const float4*)&g_h[(size_t)n * Hq + lane * 4];
    int o = g * Hq + lane * 4;
    atomicAdd(&g_psum[o + 0], v.x);
    atomicAdd(&g_psum[o + 1], v.y);
    atomicAdd(&g_psum[o + 2], v.z);
    atomicAdd(&g_psum[o + 3], v.w);
    atomicMaxFloat(&g_pmax[o + 0], v.x);
    atomicMaxFloat(&g_pmax[o + 1], v.y);
    atomicMaxFloat(&g_pmax[o + 2], v.z);
    atomicMaxFloat(&g_pmax[o + 3], v.w);
}

// ---------------- final MLP head: one block per graph ----------------
__global__ void final_mlp(const float* __restrict__ Wq1, const float* __restrict__ bq1,
                          const float* __restrict__ gq, const float* __restrict__ beq,
                          const float* __restrict__ Wq2, const float* __restrict__ bq2,
                          float* __restrict__ out)
{
    int g = blockIdx.x;
    int tid = threadIdx.x;   // 256
    __shared__ float emb[2 * Hq];
    __shared__ float p[Hq];
    __shared__ float stats[2];

    if (tid < Hq) emb[tid] = g_psum[g * Hq + tid] / fmaxf(g_cnt[g], 1.0f);
    else          emb[tid] = g_pmax[g * Hq + (tid - Hq)];
    __syncthreads();

    if (tid < Hq) {
        float t = bq1[tid];
        for (int k = 0; k < 2 * Hq; k++) t += emb[k] * Wq1[k * Hq + tid];
        p[tid] = t;
    }
    __syncthreads();

    if (tid == 0) {
        float s = 0.f;
        for (int j = 0; j < Hq; j++) s += p[j];
        float mu = s * (1.0f / 128.0f);
        float v = 0.f;
        for (int j = 0; j < Hq; j++) { float d = p[j] - mu; v += d * d; }
        stats[0] = mu;
        stats[1] = rsqrtf(v * (1.0f / 128.0f) + 1e-5f);
    }
    __syncthreads();

    if (tid < Hq) {
        float y = (p[tid] - stats[0]) * stats[1] * gq[tid] + beq[tid];
        p[tid] = gelu_exact(y);
    }
    __syncthreads();

    float o = bq2[tid];
    for (int k = 0; k < Hq; k++) o += p[k] * Wq2[k * FOUTq + tid];
    out[g * FOUTq + tid] = o;
}

// ---------------- launch ----------------
extern "C" void kernel_launch(void* const* d_in, const int* in_sizes, int n_in,
                              void* d_out, int out_size)
{
    const float* x   = (const float*)d_in[0];
    const int*   ei  = (const int*)d_in[1];
    const int*   n2g = (const int*)d_in[2];
    const float* Wp  = (const float*)d_in[3];
    const float* bp  = (const float*)d_in[4];
    const float* Wq1 = (const float*)d_in[5];
    const float* bq1 = (const float*)d_in[6];
    const float* gq  = (const float*)d_in[7];
    const float* beq = (const float*)d_in[8];
    const float* Wq2 = (const float*)d_in[9];
    const float* bq2 = (const float*)d_in[10];
    float* out = (float*)d_out;

    float *ph = nullptr, *php = nullptr;
    cudaGetSymbolAddress((void**)&ph,  g_h);
    cudaGetSymbolAddress((void**)&php, g_hp);

    const int NB_GEMM  = (Nn + 63) / 64;                       // 1563
    const int NB_NH    = (Nn * HEADSq + 255) / 256;            // 1563
    const int NB_CLR   = (Nn * Hq + 255) / 256;                // 50000
    const int NB_EDGE  = (ETOT * HEADSq + 255) / 256;          // 26563
    const int NB_SCAT  = (ETOT * 32 + 255) / 256;              // 212500
    const int NB_NODEW = (Nn * 32 + 255) / 256;                // 12500

    // input projection: h = gelu(x @ Wp + bp)
    gemm128<DINq, true, true><<<NB_GEMM, 256>>>(x, Wp, bp, ph, Nn);

    for (int L = 0; L < 2; L++) {
        const float* Wg = (const float*)d_in[11 + 6 * L];
        const float* as_ = (const float*)d_in[12 + 6 * L];
        const float* ad_ = (const float*)d_in[13 + 6 * L];
        const float* bg  = (const float*)d_in[14 + 6 * L];
        const float* ga  = (const float*)d_in[15 + 6 * L];
        const float* be  = (const float*)d_in[16 + 6 * L];

        gemm128<Hq, false, false><<<NB_GEMM, 256>>>(ph, Wg, nullptr, php, Nn);
        attn_logits<<<NB_NH, 256>>>(as_, ad_);
        clear_layer<<<NB_CLR, 256>>>();
        edge_max<<<NB_EDGE, 256>>>(ei);
        edge_exp<<<NB_EDGE, 256>>>(ei);
        edge_scatter<<<NB_SCAT, 256>>>(ei);
        post_ln<<<NB_NODEW, 256>>>(bg, ga, be);
    }

    pool_clear<<<(Gq * Hq + 255) / 256, 256>>>();
    pool_scatter<<<NB_NODEW, 256>>>(n2g);
    final_mlp<<<Gq, 256>>>(Wq1, bq1, gq, beq, Wq2, bq2, out);
}

// round 2
// speedup vs baseline: 3.3273x; 3.3273x over previous
#include <cuda_runtime.h>
#include <math.h>

#define Nn   100000
#define Ee   1600000
#define ETOT (Ee + Nn)
#define DINq 16
#define Hq   128
#define HEADSq 4
#define DOUTq  32
#define Gq   64
#define FOUTq 256

// ---- scratch (static device memory) ----
__device__ float g_h[(size_t)Nn * Hq];
__device__ float g_hp[(size_t)Nn * Hq];
__device__ float g_alS[Nn * HEADSq];
__device__ float g_alD[Nn * HEADSq];
__device__ int   g_cnt_i[Nn];
__device__ int   g_rowptr[Nn + 1];
__device__ int   g_cursor[Nn];
__device__ int   g_csr_src[ETOT];
__device__ int   g_blocksums[512];
__device__ float g_psum[Gq * Hq];
__device__ float g_pmax[Gq * Hq];
__device__ float g_gcnt[Gq];

__device__ __forceinline__ void atomicMaxFloat(float* addr, float v) {
    if (v >= 0.0f) atomicMax((int*)addr, __float_as_int(v));
    else           atomicMin((unsigned int*)addr, __float_as_uint(v));
}

__device__ __forceinline__ float gelu_exact(float v) {
    return 0.5f * v * (1.0f + erff(v * 0.70710678118654752f));
}

// ---------------- tiled GEMM: C[M x 128] = A[M x K] @ W[K x 128] ----------------
template<int K, bool DO_GELU, bool DO_BIAS>
__global__ void gemm128(const float* __restrict__ A, const float* __restrict__ W,
                        const float* __restrict__ bias, float* __restrict__ C, int M)
{
    const int BN = 64, BK = 16;
    __shared__ float As[BK][BN + 4];
    __shared__ float Ws[BK][Hq];
    int tid = threadIdx.x;            // 256 threads
    int m0  = blockIdx.x * BN;
    int c0  = (tid & 31) * 4;
    int r0  = (tid >> 5) * 8;

    float acc[8][4];
#pragma unroll
    for (int r = 0; r < 8; r++)
#pragma unroll
        for (int q = 0; q < 4; q++) acc[r][q] = 0.f;

    for (int k0 = 0; k0 < K; k0 += BK) {
        for (int i = tid; i < BN * BK; i += 256) {
            int r = i / BK, k = i % BK;
            As[k][r] = (m0 + r < M) ? A[(size_t)(m0 + r) * K + k0 + k] : 0.f;
        }
        for (int i = tid; i < BK * Hq; i += 256) {
            int k = i / Hq, c = i % Hq;
            Ws[k][c] = W[(size_t)(k0 + k) * Hq + c];
        }
        __syncthreads();
#pragma unroll
        for (int kk = 0; kk < BK; kk++) {
            float4 w  = *(const float4*)&Ws[kk][c0];
            float4 a0 = *(const float4*)&As[kk][r0];
            float4 a1 = *(const float4*)&As[kk][r0 + 4];
            float av[8] = {a0.x, a0.y, a0.z, a0.w, a1.x, a1.y, a1.z, a1.w};
#pragma unroll
            for (int r = 0; r < 8; r++) {
                acc[r][0] += av[r] * w.x;
                acc[r][1] += av[r] * w.y;
                acc[r][2] += av[r] * w.z;
                acc[r][3] += av[r] * w.w;
            }
        }
        __syncthreads();
    }

#pragma unroll
    for (int r = 0; r < 8; r++) {
        int m = m0 + r0 + r;
        if (m < M) {
            float4 o;
            float* po = &o.x;
#pragma unroll
            for (int q = 0; q < 4; q++) {
                float v = acc[r][q];
                if (DO_BIAS) v += bias[c0 + q];
                if (DO_GELU) v = gelu_exact(v);
                po[q] = v;
            }
            *(float4*)&C[(size_t)m * Hq + c0] = o;
        }
    }
}

// ---------------- attention logits per node/head ----------------
__global__ void attn_logits(const float* __restrict__ a_s, const float* __restrict__ a_d)
{
    int idx = blockIdx.x * blockDim.x + threadIdx.x;   // n*4 + head
    if (idx >= Nn * HEADSq) return;
    int n = idx >> 2, hd = idx & 3;
    const float* hrow = g_hp + (size_t)n * Hq + hd * DOUTq;
    const float* asr  = a_s + hd * DOUTq;
    const float* adr  = a_d + hd * DOUTq;
    float s1 = 0.f, s2 = 0.f;
#pragma unroll
    for (int d = 0; d < DOUTq; d += 4) {
        float4 v = *(const float4*)&hrow[d];
        float4 a = *(const float4*)&asr[d];
        float4 b = *(const float4*)&adr[d];
        s1 += v.x * a.x + v.y * a.y + v.z * a.z + v.w * a.w;
        s2 += v.x * b.x + v.y * b.y + v.z * b.z + v.w * b.w;
    }
    g_alS[idx] = s1;
    g_alD[idx] = s2;
}

// ================= CSR build =================
__global__ void zero_cnt()
{
    int i = blockIdx.x * blockDim.x + threadIdx.x;
    if (i < Nn) g_cnt_i[i] = 0;
}

__global__ void hist_dst(const int* __restrict__ ei)
{
    int e = blockIdx.x * blockDim.x + threadIdx.x;
    if (e >= ETOT) return;
    int d = (e < Ee) ? ei[Ee + e] : (e - Ee);
    atomicAdd(&g_cnt_i[d], 1);
}

__global__ void scan1()
{
    __shared__ int s[256];
    int i = blockIdx.x * 256 + threadIdx.x;
    int v = (i < Nn) ? g_cnt_i[i] : 0;
    s[threadIdx.x] = v;
    __syncthreads();
#pragma unroll
    for (int o = 1; o < 256; o <<= 1) {
        int t = (threadIdx.x >= o) ? s[threadIdx.x - o] : 0;
        __syncthreads();
        s[threadIdx.x] += t;
        __syncthreads();
    }
    if (i < Nn) g_rowptr[i] = s[threadIdx.x] - v;   // block-local exclusive
    if (threadIdx.x == 255) g_blocksums[blockIdx.x] = s[255];
}

__global__ void scan2(int nblocks)
{
    __shared__ int s[512];
    int t = threadIdx.x;
    int v = (t < nblocks) ? g_blocksums[t] : 0;
    s[t] = v;
    __syncthreads();
#pragma unroll
    for (int o = 1; o < 512; o <<= 1) {
        int u = (t >= o) ? s[t - o] : 0;
        __syncthreads();
        s[t] += u;
        __syncthreads();
    }
    if (t < nblocks) g_blocksums[t] = s[t] - v;    // exclusive
}

__global__ void scan3()
{
    int i = blockIdx.x * 256 + threadIdx.x;
    if (i < Nn) {
        int r = g_rowptr[i] + g_blocksums[blockIdx.x];
        g_rowptr[i] = r;
        g_cursor[i] = r;
    }
    if (i == 0) g_rowptr[Nn] = ETOT;
}

__global__ void csr_fill(const int* __restrict__ ei)
{
    int e = blockIdx.x * blockDim.x + threadIdx.x;
    if (e >= ETOT) return;
    int s, d;
    if (e < Ee) { s = ei[e]; d = ei[Ee + e]; } else { s = d = e - Ee; }
    int pos = atomicAdd(&g_cursor[d], 1);
    g_csr_src[pos] = s;
}

// ====== fused GAT aggregation + bias + residual + LayerNorm (warp per node) ======
__global__ void gat_agg_ln(const float* __restrict__ bg, const float* __restrict__ ga,
                           const float* __restrict__ be)
{
    int n = blockIdx.x * 8 + (threadIdx.x >> 5);
    if (n >= Nn) return;
    int lane = threadIdx.x & 31;
    int start = g_rowptr[n];
    int end   = g_rowptr[n + 1];

    float4 adv = *(const float4*)&g_alD[n * 4];
    float ad0 = adv.x, ad1 = adv.y, ad2 = adv.z, ad3 = adv.w;

    // pass 1: softmax denominators per head (no max-shift; logits are O(1))
    float den0 = 0.f, den1 = 0.f, den2 = 0.f, den3 = 0.f;
    for (int i = start + lane; i < end; i += 32) {
        int s = g_csr_src[i];
        float4 asv = *(const float4*)&g_alS[s * 4];
        float l0 = asv.x + ad0; l0 = (l0 > 0.f) ? l0 : 0.2f * l0;
        float l1 = asv.y + ad1; l1 = (l1 > 0.f) ? l1 : 0.2f * l1;
        float l2 = asv.z + ad2; l2 = (l2 > 0.f) ? l2 : 0.2f * l2;
        float l3 = asv.w + ad3; l3 = (l3 > 0.f) ? l3 : 0.2f * l3;
        den0 += __expf(l0); den1 += __expf(l1);
        den2 += __expf(l2); den3 += __expf(l3);
    }
#pragma unroll
    for (int o = 16; o; o >>= 1) {
        den0 += __shfl_xor_sync(0xffffffffu, den0, o);
        den1 += __shfl_xor_sync(0xffffffffu, den1, o);
        den2 += __shfl_xor_sync(0xffffffffu, den2, o);
        den3 += __shfl_xor_sync(0xffffffffu, den3, o);
    }

    int hd = lane >> 3;                 // this lane's 4 dims belong to head hd
    float denh = (hd == 0) ? den0 : (hd == 1) ? den1 : (hd == 2) ? den2 : den3;
    float adh  = (hd == 0) ? ad0  : (hd == 1) ? ad1  : (hd == 2) ? ad2  : ad3;
    float dinv = 1.0f / (denh + 1e-16f);

    // pass 2: weighted gather-accumulate (edges sequential, lanes cover dims)
    float a0 = 0.f, a1 = 0.f, a2 = 0.f, a3 = 0.f;
    for (int i = start; i < end; i++) {
        int s = g_csr_src[i];                      // warp-broadcast load
        float l = g_alS[s * 4 + hd] + adh;
        l = (l > 0.f) ? l : 0.2f * l;
        float alpha = __expf(l) * dinv;
        float4 v = *(const float4*)&g_hp[(size_t)s * Hq + lane * 4];
        a0 += v.x * alpha; a1 += v.y * alpha;
        a2 += v.z * alpha; a3 += v.w * alpha;
    }

    // epilogue: bias + residual + layernorm
    size_t base = (size_t)n * Hq + lane * 4;
    float4 hv = *(const float4*)&g_h[base];
    float4 b4 = *(const float4*)&bg[lane * 4];
    float v0 = a0 + b4.x + hv.x;
    float v1 = a1 + b4.y + hv.y;
    float v2 = a2 + b4.z + hv.z;
    float v3 = a3 + b4.w + hv.w;

    float s = v0 + v1 + v2 + v3;
#pragma unroll
    for (int o = 16; o; o >>= 1) s += __shfl_xor_sync(0xffffffffu, s, o);
    float mu = s * (1.0f / 128.0f);
    float d0 = v0 - mu, d1 = v1 - mu, d2 = v2 - mu, d3 = v3 - mu;
    float q = d0 * d0 + d1 * d1 + d2 * d2 + d3 * d3;
#pragma unroll
    for (int o = 16; o; o >>= 1) q += __shfl_xor_sync(0xffffffffu, q, o);
    float rs = rsqrtf(q * (1.0f / 128.0f) + 1e-5f);

    float4 g4 = *(const float4*)&ga[lane * 4];
    float4 e4 = *(const float4*)&be[lane * 4];
    float4 outv;
    outv.x = d0 * rs * g4.x + e4.x;
    outv.y = d1 * rs * g4.y + e4.y;
    outv.z = d2 * rs * g4.z + e4.z;
    outv.w = d3 * rs * g4.w + e4.w;
    *(float4*)&g_h[base] = outv;
}

// ---------------- pooling (two-stage: register accumulate, atomic per segment) ----
__global__ void pool_clear()
{
    int idx = blockIdx.x * blockDim.x + threadIdx.x;
    if (idx < Gq * Hq) { g_psum[idx] = 0.f; g_pmax[idx] = -INFINITY; }
    if (idx < Gq) g_gcnt[idx] = 0.f;
}

__global__ void pool_chunk(const int* __restrict__ n2g)
{
    // 128 threads (one per dim), block per 256-node chunk
    __shared__ int sg[256];
    int d  = threadIdx.x;
    int n0 = blockIdx.x * 256;
    int n1 = n0 + 256; if (n1 > Nn) n1 = Nn;
    int cn = n1 - n0;
    for (int i = d; i < cn; i += 128) sg[i] = n2g[n0 + i];
    __syncthreads();

    int   curg = sg[0];
    float sum = 0.f, mx = -INFINITY;
    int   cnt = 0;
    for (int j = 0; j < cn; j++) {
        int g = sg[j];
        if (g != curg) {
            atomicAdd(&g_psum[curg * Hq + d], sum);
            atomicMaxFloat(&g_pmax[curg * Hq + d], mx);
            if (d == 0) atomicAdd(&g_gcnt[curg], (float)cnt);
            sum = 0.f; mx = -INFINITY; cnt = 0; curg = g;
        }
        float v = g_h[(size_t)(n0 + j) * Hq + d];
        sum += v; mx = fmaxf(mx, v); cnt++;
    }
    atomicAdd(&g_psum[curg * Hq + d], sum);
    atomicMaxFloat(&g_pmax[curg * Hq + d], mx);
    if (d == 0) atomicAdd(&g_gcnt[curg], (float)cnt);
}

// ---------------- final MLP head: one block per graph ----------------
__global__ void final_mlp(const float* __restrict__ Wq1, const float* __restrict__ bq1,
                          const float* __restrict__ gq, const float* __restrict__ beq,
                          const float* __restrict__ Wq2, const float* __restrict__ bq2,
                          float* __restrict__ out)
{
    int g = blockIdx.x;
    int tid = threadIdx.x;   // 256
    __shared__ float emb[2 * Hq];
    __shared__ float p[Hq];
    __shared__ float stats[2];

    if (tid < Hq) emb[tid] = g_psum[g * Hq + tid] / fmaxf(g_gcnt[g], 1.0f);
    else          emb[tid] = g_pmax[g * Hq + (tid - Hq)];
    __syncthreads();

    if (tid < Hq) {
        float t = bq1[tid];
        for (int k = 0; k < 2 * Hq; k++) t += emb[k] * Wq1[k * Hq + tid];
        p[tid] = t;
    }
    __syncthreads();

    if (tid == 0) {
        float s = 0.f;
        for (int j = 0; j < Hq; j++) s += p[j];
        float mu = s * (1.0f / 128.0f);
        float v = 0.f;
        for (int j = 0; j < Hq; j++) { float dd = p[j] - mu; v += dd * dd; }
        stats[0] = mu;
        stats[1] = rsqrtf(v * (1.0f / 128.0f) + 1e-5f);
    }
    __syncthreads();

    if (tid < Hq) {
        float y = (p[tid] - stats[0]) * stats[1] * gq[tid] + beq[tid];
        p[tid] = gelu_exact(y);
    }
    __syncthreads();

    float o = bq2[tid];
    for (int k = 0; k < Hq; k++) o += p[k] * Wq2[k * FOUTq + tid];
    out[g * FOUTq + tid] = o;
}

// ---------------- launch ----------------
extern "C" void kernel_launch(void* const* d_in, const int* in_sizes, int n_in,
                              void* d_out, int out_size)
{
    const float* x   = (const float*)d_in[0];
    const int*   ei  = (const int*)d_in[1];
    const int*   n2g = (const int*)d_in[2];
    const float* Wp  = (const float*)d_in[3];
    const float* bp  = (const float*)d_in[4];
    const float* Wq1 = (const float*)d_in[5];
    const float* bq1 = (const float*)d_in[6];
    const float* gq  = (const float*)d_in[7];
    const float* beq = (const float*)d_in[8];
    const float* Wq2 = (const float*)d_in[9];
    const float* bq2 = (const float*)d_in[10];
    float* out = (float*)d_out;

    float *ph = nullptr, *php = nullptr;
    cudaGetSymbolAddress((void**)&ph,  g_h);
    cudaGetSymbolAddress((void**)&php, g_hp);

    const int NB_GEMM = (Nn + 63) / 64;
    const int NB_NH   = (Nn * HEADSq + 255) / 256;
    const int NB_N    = (Nn + 255) / 256;            // 391
    const int NB_E    = (ETOT + 255) / 256;
    const int NB_AGG  = (Nn + 7) / 8;                // 8 warps (nodes) per block
    const int NB_POOL = (Nn + 255) / 256;

    // ---- CSR build (by dst, self-loops included) ----
    zero_cnt<<<NB_N, 256>>>();
    hist_dst<<<NB_E, 256>>>(ei);
    scan1<<<NB_N, 256>>>();
    scan2<<<1, 512>>>(NB_N);
    scan3<<<NB_N, 256>>>();
    csr_fill<<<NB_E, 256>>>(ei);

    // ---- input projection: h = gelu(x @ Wp + bp) ----
    gemm128<DINq, true, true><<<NB_GEMM, 256>>>(x, Wp, bp, ph, Nn);

    for (int L = 0; L < 2; L++) {
        const float* Wg  = (const float*)d_in[11 + 6 * L];
        const float* as_ = (const float*)d_in[12 + 6 * L];
        const float* ad_ = (const float*)d_in[13 + 6 * L];
        const float* bg  = (const float*)d_in[14 + 6 * L];
        const float* ga  = (const float*)d_in[15 + 6 * L];
        const float* be  = (const float*)d_in[16 + 6 * L];

        gemm128<Hq, false, false><<<NB_GEMM, 256>>>(ph, Wg, nullptr, php, Nn);
        attn_logits<<<NB_NH, 256>>>(as_, ad_);
        gat_agg_ln<<<NB_AGG, 256>>>(bg, ga, be);
    }

    pool_clear<<<(Gq * Hq + 255) / 256, 256>>>();
    pool_chunk<<<NB_POOL, 128>>>(n2g);
    final_mlp<<<Gq, 256>>>(Wq1, bq1, gq, beq, Wq2, bq2, out);
}

// round 3
// speedup vs baseline: 3.8444x; 1.1554x over previous
#include <cuda_runtime.h>
#include <math.h>

#define Nn   100000
#define Ee   1600000
#define ETOT (Ee + Nn)
#define DINq 16
#define Hq   128
#define HEADSq 4
#define DOUTq  32
#define Gq   64
#define FOUTq 256

typedef unsigned long long u64;

// ---- scratch (static device memory) ----
__device__ float g_h[(size_t)Nn * Hq];
__device__ float g_hp[(size_t)Nn * Hq];
__device__ float g_alS[Nn * HEADSq];
__device__ float g_alD[Nn * HEADSq];
__device__ int   g_cnt_i[Nn];
__device__ int   g_rowptr[Nn + 1];
__device__ int   g_cursor[Nn];
__device__ int   g_csr_src[ETOT];
__device__ int   g_blocksums[512];
__device__ float g_psum[Gq * Hq];
__device__ float g_pmax[Gq * Hq];
__device__ float g_gcnt[Gq];

__device__ __forceinline__ void atomicMaxFloat(float* addr, float v) {
    if (v >= 0.0f) atomicMax((int*)addr, __float_as_int(v));
    else           atomicMin((unsigned int*)addr, __float_as_uint(v));
}

__device__ __forceinline__ float gelu_exact(float v) {
    return 0.5f * v * (1.0f + erff(v * 0.70710678118654752f));
}

// ---- packed f32x2 helpers (Blackwell FFMA2; PTX-only, ptxas won't auto-fuse) ----
__device__ __forceinline__ void pfma(u64& d, u64 a, u64 b) {
    asm("fma.rn.f32x2 %0, %1, %2, %0;" : "+l"(d) : "l"(a), "l"(b));
}
__device__ __forceinline__ u64 pk(float lo, float hi) {
    u64 r; asm("mov.b64 %0, {%1,%2};" : "=l"(r) : "f"(lo), "f"(hi)); return r;
}
__device__ __forceinline__ void upk(u64 p, float& lo, float& hi) {
    asm("mov.b64 {%0,%1}, %2;" : "=f"(lo), "=f"(hi) : "l"(p));
}

// ------- tiled GEMM: C[M x 128] = A[M x K] @ W[K x 128], packed-f32x2 inner -------
// Optional fused epilogue: attention logits alS/alD (per node, per head).
template<int K, bool DO_GELU, bool DO_BIAS, bool DO_ATTN>
__global__ void gemm128(const float* __restrict__ A, const float* __restrict__ W,
                        const float* __restrict__ bias,
                        const float* __restrict__ a_s, const float* __restrict__ a_d,
                        float* __restrict__ C, int M)
{
    const int BN = 64, BK = 16;
    __shared__ float As[BK][BN + 4];
    __shared__ float Ws[BK][Hq];
    int tid  = threadIdx.x;           // 256 threads
    int lane = tid & 31;
    int m0   = blockIdx.x * BN;
    int c0   = lane * 4;              // this lane's 4 output cols
    int r0   = (tid >> 5) * 8;        // this warp's 8 rows

    // acc[rp][q] packs rows (r0+2rp, r0+2rp+1) at col c0+q
    u64 acc[4][4];
#pragma unroll
    for (int rp = 0; rp < 4; rp++)
#pragma unroll
        for (int q = 0; q < 4; q++) acc[rp][q] = 0ull;

    for (int k0 = 0; k0 < K; k0 += BK) {
        for (int i = tid; i < BN * BK; i += 256) {
            int r = i / BK, k = i % BK;
            As[k][r] = (m0 + r < M) ? A[(size_t)(m0 + r) * K + k0 + k] : 0.f;
        }
        for (int i = tid; i < BK * Hq; i += 256) {
            int k = i / Hq, c = i % Hq;
            Ws[k][c] = W[(size_t)(k0 + k) * Hq + c];
        }
        __syncthreads();
#pragma unroll
        for (int kk = 0; kk < BK; kk++) {
            float4 w  = *(const float4*)&Ws[kk][c0];
            u64 w0 = pk(w.x, w.x), w1 = pk(w.y, w.y);
            u64 w2 = pk(w.z, w.z), w3 = pk(w.w, w.w);
            float4 a0 = *(const float4*)&As[kk][r0];
            float4 a1 = *(const float4*)&As[kk][r0 + 4];
            u64 ap[4] = {pk(a0.x, a0.y), pk(a0.z, a0.w),
                         pk(a1.x, a1.y), pk(a1.z, a1.w)};
#pragma unroll
            for (int rp = 0; rp < 4; rp++) {
                pfma(acc[rp][0], ap[rp], w0);
                pfma(acc[rp][1], ap[rp], w1);
                pfma(acc[rp][2], ap[rp], w2);
                pfma(acc[rp][3], ap[rp], w3);
            }
        }
        __syncthreads();
    }

    // unpack to v[r][q]
    float v[8][4];
#pragma unroll
    for (int rp = 0; rp < 4; rp++)
#pragma unroll
        for (int q = 0; q < 4; q++)
            upk(acc[rp][q], v[2 * rp][q], v[2 * rp + 1][q]);

#pragma unroll
    for (int r = 0; r < 8; r++) {
        int m = m0 + r0 + r;
        if (m < M) {
            float4 o;
            float* po = &o.x;
#pragma unroll
            for (int q = 0; q < 4; q++) {
                float t = v[r][q];
                if (DO_BIAS) t += bias[c0 + q];
                if (DO_GELU) t = gelu_exact(t);
                po[q] = t;
                v[r][q] = t;
            }
            *(float4*)&C[(size_t)m * Hq + c0] = o;
        }
    }

    if (DO_ATTN) {
        // a_s/a_d are [HEADS][DOUT] = 128 contiguous floats; col c maps directly.
        float4 asv = *(const float4*)&a_s[c0];
        float4 adv = *(const float4*)&a_d[c0];
        int head = lane >> 3;          // 8 lanes per head
#pragma unroll
        for (int r = 0; r < 8; r++) {
            float ps = v[r][0] * asv.x + v[r][1] * asv.y + v[r][2] * asv.z + v[r][3] * asv.w;
            float pd = v[r][0] * adv.x + v[r][1] * adv.y + v[r][2] * adv.z + v[r][3] * adv.w;
#pragma unroll
            for (int o = 1; o < 8; o <<= 1) {
                ps += __shfl_xor_sync(0xffffffffu, ps, o);
                pd += __shfl_xor_sync(0xffffffffu, pd, o);
            }
            int m = m0 + r0 + r;
            if ((lane & 7) == 0 && m < M) {
                g_alS[m * 4 + head] = ps;
                g_alD[m * 4 + head] = pd;
            }
        }
    }
}

// ================= CSR build =================
__global__ void zero_cnt()
{
    int i = blockIdx.x * blockDim.x + threadIdx.x;
    if (i < Nn) g_cnt_i[i] = 0;
}

__global__ void hist_dst(const int* __restrict__ ei)
{
    int e = blockIdx.x * blockDim.x + threadIdx.x;
    if (e >= ETOT) return;
    int d = (e < Ee) ? ei[Ee + e] : (e - Ee);
    atomicAdd(&g_cnt_i[d], 1);
}

__global__ void scan1()
{
    __shared__ int s[256];
    int i = blockIdx.x * 256 + threadIdx.x;
    int v = (i < Nn) ? g_cnt_i[i] : 0;
    s[threadIdx.x] = v;
    __syncthreads();
#pragma unroll
    for (int o = 1; o < 256; o <<= 1) {
        int t = (threadIdx.x >= o) ? s[threadIdx.x - o] : 0;
        __syncthreads();
        s[threadIdx.x] += t;
        __syncthreads();
    }
    if (i < Nn) g_rowptr[i] = s[threadIdx.x] - v;   // block-local exclusive
    if (threadIdx.x == 255) g_blocksums[blockIdx.x] = s[255];
}

__global__ void scan2(int nblocks)
{
    __shared__ int s[512];
    int t = threadIdx.x;
    int v = (t < nblocks) ? g_blocksums[t] : 0;
    s[t] = v;
    __syncthreads();
#pragma unroll
    for (int o = 1; o < 512; o <<= 1) {
        int u = (t >= o) ? s[t - o] : 0;
        __syncthreads();
        s[t] += u;
        __syncthreads();
    }
    if (t < nblocks) g_blocksums[t] = s[t] - v;    // exclusive
}

__global__ void scan3()
{
    int i = blockIdx.x * 256 + threadIdx.x;
    if (i < Nn) {
        int r = g_rowptr[i] + g_blocksums[blockIdx.x];
        g_rowptr[i] = r;
        g_cursor[i] = r;
    }
    if (i == 0) g_rowptr[Nn] = ETOT;
}

__global__ void csr_fill(const int* __restrict__ ei)
{
    int e = blockIdx.x * blockDim.x + threadIdx.x;
    if (e >= ETOT) return;
    int s, d;
    if (e < Ee) { s = ei[e]; d = ei[Ee + e]; } else { s = d = e - Ee; }
    int pos = atomicAdd(&g_cursor[d], 1);
    g_csr_src[pos] = s;
}

// ====== fused GAT aggregation + bias + residual + LayerNorm (warp per node) ======
__global__ void gat_agg_ln(const float* __restrict__ bg, const float* __restrict__ ga,
                           const float* __restrict__ be)
{
    int n = blockIdx.x * 8 + (threadIdx.x >> 5);
    if (n >= Nn) return;
    int lane = threadIdx.x & 31;
    int start = g_rowptr[n];
    int end   = g_rowptr[n + 1];

    float4 adv = *(const float4*)&g_alD[n * 4];
    float ad0 = adv.x, ad1 = adv.y, ad2 = adv.z, ad3 = adv.w;

    // pass 1: softmax denominators per head (no max-shift; logits are O(1))
    float den0 = 0.f, den1 = 0.f, den2 = 0.f, den3 = 0.f;
    for (int i = start + lane; i < end; i += 32) {
        int s = g_csr_src[i];
        float4 asv = *(const float4*)&g_alS[s * 4];
        float l0 = asv.x + ad0; l0 = (l0 > 0.f) ? l0 : 0.2f * l0;
        float l1 = asv.y + ad1; l1 = (l1 > 0.f) ? l1 : 0.2f * l1;
        float l2 = asv.z + ad2; l2 = (l2 > 0.f) ? l2 : 0.2f * l2;
        float l3 = asv.w + ad3; l3 = (l3 > 0.f) ? l3 : 0.2f * l3;
        den0 += __expf(l0); den1 += __expf(l1);
        den2 += __expf(l2); den3 += __expf(l3);
    }
#pragma unroll
    for (int o = 16; o; o >>= 1) {
        den0 += __shfl_xor_sync(0xffffffffu, den0, o);
        den1 += __shfl_xor_sync(0xffffffffu, den1, o);
        den2 += __shfl_xor_sync(0xffffffffu, den2, o);
        den3 += __shfl_xor_sync(0xffffffffu, den3, o);
    }

    int hd = lane >> 3;                 // this lane's 4 dims belong to head hd
    float denh = (hd == 0) ? den0 : (hd == 1) ? den1 : (hd == 2) ? den2 : den3;
    float adh  = (hd == 0) ? ad0  : (hd == 1) ? ad1  : (hd == 2) ? ad2  : ad3;
    float dinv = 1.0f / (denh + 1e-16f);

    // pass 2: weighted gather-accumulate, unrolled by 2 for MLP
    float a0 = 0.f, a1 = 0.f, a2 = 0.f, a3 = 0.f;
    int i = start;
    for (; i + 1 < end; i += 2) {
        int s0 = g_csr_src[i];
        int s1 = g_csr_src[i + 1];
        float la = g_alS[s0 * 4 + hd] + adh;
        float lb = g_alS[s1 * 4 + hd] + adh;
        la = (la > 0.f) ? la : 0.2f * la;
        lb = (lb > 0.f) ? lb : 0.2f * lb;
        float al0 = __expf(la) * dinv;
        float al1 = __expf(lb) * dinv;
        float4 v0 = *(const float4*)&g_hp[(size_t)s0 * Hq + lane * 4];
        float4 v1 = *(const float4*)&g_hp[(size_t)s1 * Hq + lane * 4];
        a0 += v0.x * al0 + v1.x * al1;
        a1 += v0.y * al0 + v1.y * al1;
        a2 += v0.z * al0 + v1.z * al1;
        a3 += v0.w * al0 + v1.w * al1;
    }
    if (i < end) {
        int s0 = g_csr_src[i];
        float la = g_alS[s0 * 4 + hd] + adh;
        la = (la > 0.f) ? la : 0.2f * la;
        float al0 = __expf(la) * dinv;
        float4 v0 = *(const float4*)&g_hp[(size_t)s0 * Hq + lane * 4];
        a0 += v0.x * al0; a1 += v0.y * al0;
        a2 += v0.z * al0; a3 += v0.w * al0;
    }

    // epilogue: bias + residual + layernorm
    size_t base = (size_t)n * Hq + lane * 4;
    float4 hv = *(const float4*)&g_h[base];
    float4 b4 = *(const float4*)&bg[lane * 4];
    float v0 = a0 + b4.x + hv.x;
    float v1 = a1 + b4.y + hv.y;
    float v2 = a2 + b4.z + hv.z;
    float v3 = a3 + b4.w + hv.w;

    float s = v0 + v1 + v2 + v3;
#pragma unroll
    for (int o = 16; o; o >>= 1) s += __shfl_xor_sync(0xffffffffu, s, o);
    float mu = s * (1.0f / 128.0f);
    float d0 = v0 - mu, d1 = v1 - mu, d2 = v2 - mu, d3 = v3 - mu;
    float q = d0 * d0 + d1 * d1 + d2 * d2 + d3 * d3;
#pragma unroll
    for (int o = 16; o; o >>= 1) q += __shfl_xor_sync(0xffffffffu, q, o);
    float rs = rsqrtf(q * (1.0f / 128.0f) + 1e-5f);

    float4 g4 = *(const float4*)&ga[lane * 4];
    float4 e4 = *(const float4*)&be[lane * 4];
    float4 outv;
    outv.x = d0 * rs * g4.x + e4.x;
    outv.y = d1 * rs * g4.y + e4.y;
    outv.z = d2 * rs * g4.z + e4.z;
    outv.w = d3 * rs * g4.w + e4.w;
    *(float4*)&g_h[base] = outv;
}

// ---------------- pooling ----------------
__global__ void pool_clear()
{
    int idx = blockIdx.x * blockDim.x + threadIdx.x;
    if (idx < Gq * Hq) { g_psum[idx] = 0.f; g_pmax[idx] = -INFINITY; }
    if (idx < Gq) g_gcnt[idx] = 0.f;
}

__global__ void pool_chunk(const int* __restrict__ n2g)
{
    __shared__ int sg[256];
    int d  = threadIdx.x;
    int n0 = blockIdx.x * 256;
    int n1 = n0 + 256; if (n1 > Nn) n1 = Nn;
    int cn = n1 - n0;
    for (int i = d; i < cn; i += 128) sg[i] = n2g[n0 + i];
    __syncthreads();

    int   curg = sg[0];
    float sum = 0.f, mx = -INFINITY;
    int   cnt = 0;
    for (int j = 0; j < cn; j++) {
        int g = sg[j];
        if (g != curg) {
            atomicAdd(&g_psum[curg * Hq + d], sum);
            atomicMaxFloat(&g_pmax[curg * Hq + d], mx);
            if (d == 0) atomicAdd(&g_gcnt[curg], (float)cnt);
            sum = 0.f; mx = -INFINITY; cnt = 0; curg = g;
        }
        float v = g_h[(size_t)(n0 + j) * Hq + d];
        sum += v; mx = fmaxf(mx, v); cnt++;
    }
    atomicAdd(&g_psum[curg * Hq + d], sum);
    atomicMaxFloat(&g_pmax[curg * Hq + d], mx);
    if (d == 0) atomicAdd(&g_gcnt[curg], (float)cnt);
}

// ---------------- final MLP head ----------------
__global__ void final_mlp(const float* __restrict__ Wq1, const float* __restrict__ bq1,
                          const float* __restrict__ gq, const float* __restrict__ beq,
                          const float* __restrict__ Wq2, const float* __restrict__ bq2,
                          float* __restrict__ out)
{
    int g = blockIdx.x;
    int tid = threadIdx.x;   // 256
    __shared__ float emb[2 * Hq];
    __shared__ float p[Hq];
    __shared__ float stats[2];

    if (tid < Hq) emb[tid] = g_psum[g * Hq + tid] / fmaxf(g_gcnt[g], 1.0f);
    else          emb[tid] = g_pmax[g * Hq + (tid - Hq)];
    __syncthreads();

    if (tid < Hq) {
        float t = bq1[tid];
        for (int k = 0; k < 2 * Hq; k++) t += emb[k] * Wq1[k * Hq + tid];
        p[tid] = t;
    }
    __syncthreads();

    if (tid == 0) {
        float s = 0.f;
        for (int j = 0; j < Hq; j++) s += p[j];
        float mu = s * (1.0f / 128.0f);
        float v = 0.f;
        for (int j = 0; j < Hq; j++) { float dd = p[j] - mu; v += dd * dd; }
        stats[0] = mu;
        stats[1] = rsqrtf(v * (1.0f / 128.0f) + 1e-5f);
    }
    __syncthreads();

    if (tid < Hq) {
        float y = (p[tid] - stats[0]) * stats[1] * gq[tid] + beq[tid];
        p[tid] = gelu_exact(y);
    }
    __syncthreads();

    float o = bq2[tid];
    for (int k = 0; k < Hq; k++) o += p[k] * Wq2[k * FOUTq + tid];
    out[g * FOUTq + tid] = o;
}

// ---------------- launch ----------------
extern "C" void kernel_launch(void* const* d_in, const int* in_sizes, int n_in,
                              void* d_out, int out_size)
{
    const float* x   = (const float*)d_in[0];
    const int*   ei  = (const int*)d_in[1];
    const int*   n2g = (const int*)d_in[2];
    const float* Wp  = (const float*)d_in[3];
    const float* bp  = (const float*)d_in[4];
    const float* Wq1 = (const float*)d_in[5];
    const float* bq1 = (const float*)d_in[6];
    const float* gq  = (const float*)d_in[7];
    const float* beq = (const float*)d_in[8];
    const float* Wq2 = (const float*)d_in[9];
    const float* bq2 = (const float*)d_in[10];
    float* out = (float*)d_out;

    float *ph = nullptr, *php = nullptr;
    cudaGetSymbolAddress((void**)&ph,  g_h);
    cudaGetSymbolAddress((void**)&php, g_hp);

    // one-time host-side infrastructure (no device allocations)
    static cudaStream_t s2 = nullptr;
    static cudaEvent_t evA = nullptr, evB = nullptr;
    if (s2 == nullptr) {
        cudaStreamCreateWithFlags(&s2, cudaStreamNonBlocking);
        cudaEventCreateWithFlags(&evA, cudaEventDisableTiming);
        cudaEventCreateWithFlags(&evB, cudaEventDisableTiming);
    }

    const int NB_GEMM = (Nn + 63) / 64;
    const int NB_N    = (Nn + 255) / 256;
    const int NB_E    = (ETOT + 255) / 256;
    const int NB_AGG  = (Nn + 7) / 8;
    const int NB_POOL = (Nn + 255) / 256;

    // ---- fork CSR build onto side stream (overlaps with GEMM path) ----
    cudaEventRecord(evA, 0);
    cudaStreamWaitEvent(s2, evA, 0);
    zero_cnt<<<NB_N, 256, 0, s2>>>();
    hist_dst<<<NB_E, 256, 0, s2>>>(ei);
    scan1<<<NB_N, 256, 0, s2>>>();
    scan2<<<1, 512, 0, s2>>>(NB_N);
    scan3<<<NB_N, 256, 0, s2>>>();
    csr_fill<<<NB_E, 256, 0, s2>>>(ei);
    cudaEventRecord(evB, s2);

    // ---- main path: projection + layer-0 GEMM (attn fused) ----
    gemm128<DINq, true, true, false><<<NB_GEMM, 256>>>(x, Wp, bp, nullptr, nullptr, ph, Nn);

    {
        const float* Wg  = (const float*)d_in[11];
        const float* as_ = (const float*)d_in[12];
        const float* ad_ = (const float*)d_in[13];
        gemm128<Hq, false, false, true><<<NB_GEMM, 256>>>(ph, Wg, nullptr, as_, ad_, php, Nn);
    }

    cudaStreamWaitEvent(0, evB, 0);   // join: aggregation needs CSR

    gat_agg_ln<<<NB_AGG, 256>>>((const float*)d_in[14], (const float*)d_in[15],
                                (const float*)d_in[16]);

    {
        const float* Wg  = (const float*)d_in[17];
        const float* as_ = (const float*)d_in[18];
        const float* ad_ = (const float*)d_in[19];
        gemm128<Hq, false, false, true><<<NB_GEMM, 256>>>(ph, Wg, nullptr, as_, ad_, php, Nn);
    }
    gat_agg_ln<<<NB_AGG, 256>>>((const float*)d_in[20], (const float*)d_in[21],
                                (const float*)d_in[22]);

    pool_clear<<<(Gq * Hq + 255) / 256, 256>>>();
    pool_chunk<<<NB_POOL, 128>>>(n2g);
    final_mlp<<<Gq, 256>>>(Wq1, bq1, gq, beq, Wq2, bq2, out);
}

// round 4
// speedup vs baseline: 3.9324x; 1.0229x over previous
#include <cuda_runtime.h>
#include <cuda_bf16.h>
#include <math.h>

#define Nn   100000
#define Ee   1600000
#define ETOT (Ee + Nn)
#define DINq 16
#define Hq   128
#define HEADSq 4
#define DOUTq  32
#define Gq   64
#define FOUTq 256

typedef unsigned long long u64;
typedef unsigned int u32;

// ---- scratch (static device memory) ----
__device__ float g_h[(size_t)Nn * Hq];        // fp32 node features
__device__ u32   g_hpb[(size_t)Nn * (Hq / 2)]; // bf16x2 packed h@Wg
__device__ float g_alS[Nn * HEADSq];
__device__ float g_alD[Nn * HEADSq];
__device__ int   g_cnt_i[Nn];
__device__ int   g_rowptr[Nn + 1];
__device__ int   g_cursor[Nn];
__device__ int   g_csr_src[ETOT];
__device__ int   g_blocksums[512];
__device__ float g_psum[Gq * Hq];
__device__ float g_pmax[Gq * Hq];
__device__ float g_gcnt[Gq];

__device__ __forceinline__ void atomicMaxFloat(float* addr, float v) {
    if (v >= 0.0f) atomicMax((int*)addr, __float_as_int(v));
    else           atomicMin((unsigned int*)addr, __float_as_uint(v));
}

__device__ __forceinline__ float gelu_exact(float v) {
    return 0.5f * v * (1.0f + erff(v * 0.70710678118654752f));
}

// ---- packed f32x2 helpers (Blackwell FFMA2) ----
__device__ __forceinline__ void pfma(u64& d, u64 a, u64 b) {
    asm("fma.rn.f32x2 %0, %1, %2, %0;" : "+l"(d) : "l"(a), "l"(b));
}
__device__ __forceinline__ u64 pku(u32 lo, u32 hi) {
    u64 r; asm("mov.b64 %0, {%1,%2};" : "=l"(r) : "r"(lo), "r"(hi)); return r;
}
__device__ __forceinline__ u64 swap64(u64 p) {
    return pku((u32)(p >> 32), (u32)p);
}
__device__ __forceinline__ float lo32(u64 p) { return __uint_as_float((u32)p); }
__device__ __forceinline__ float hi32(u64 p) { return __uint_as_float((u32)(p >> 32)); }
__device__ __forceinline__ u32 bfpack(float lo, float hi) {
    u32 r; asm("cvt.rn.bf16x2.f32 %0, %1, %2;" : "=r"(r) : "f"(hi), "f"(lo)); return r;
}

// ------- tiled GEMM: [M x 128] = A[M x K] @ W[K x 128], 8x8/thread FFMA2 -------
// Epilogue options: gelu+bias -> fp32 C; or attn logits + bf16 store.
template<int K, bool DO_GELU, bool DO_ATTN, bool OUT_BF16>
__global__ void gemm128T(const float* __restrict__ A, const float* __restrict__ W,
                         const float* __restrict__ bias,
                         const float* __restrict__ a_s, const float* __restrict__ a_d,
                         float* __restrict__ C, int M)
{
    const int BN = 128, BK = 16;
    __shared__ float As[BK][BN + 4];
    __shared__ float Ws[BK][Hq + 4];
    int tid = threadIdx.x;            // 256 threads
    int tx = tid & 15, ty = tid >> 4;
    int lane = tid & 31;
    int m0 = blockIdx.x * BN;
    int c0 = tx * 8;                  // 8 output cols
    int r0 = ty * 8;                  // 8 output rows

    // acc[rp][cp][d]: rp=row pair (r0+2rp, +1), cp=col pair (c0+2cp, +1)
    // d=0: (r0c0, r1c1) diagonal; d=1: (r0c1, r1c0) anti-diagonal
    u64 acc[4][4][2];
#pragma unroll
    for (int rp = 0; rp < 4; rp++)
#pragma unroll
        for (int cp = 0; cp < 4; cp++) { acc[rp][cp][0] = 0ull; acc[rp][cp][1] = 0ull; }

    for (int k0 = 0; k0 < K; k0 += BK) {
#pragma unroll
        for (int i = tid; i < BN * BK; i += 256) {
            int r = i >> 4, k = i & 15;
            As[k][r] = (m0 + r < M) ? A[(size_t)(m0 + r) * K + k0 + k] : 0.f;
        }
#pragma unroll
        for (int i = tid; i < BK * Hq; i += 256) {
            int k = i >> 7, c = i & 127;
            Ws[k][c] = W[(size_t)(k0 + k) * Hq + c];
        }
        __syncthreads();
#pragma unroll
        for (int kk = 0; kk < BK; kk++) {
            ulonglong2 ra = *(const ulonglong2*)&As[kk][r0];      // row pairs 0,1
            ulonglong2 rb = *(const ulonglong2*)&As[kk][r0 + 4];  // row pairs 2,3
            ulonglong2 wa = *(const ulonglong2*)&Ws[kk][c0];      // col pairs 0,1
            ulonglong2 wb = *(const ulonglong2*)&Ws[kk][c0 + 4];  // col pairs 2,3
            u64 rr[4] = {ra.x, ra.y, rb.x, rb.y};
            u64 cn[4] = {wa.x, wa.y, wb.x, wb.y};
            u64 cs[4] = {swap64(wa.x), swap64(wa.y), swap64(wb.x), swap64(wb.y)};
#pragma unroll
            for (int rp = 0; rp < 4; rp++)
#pragma unroll
                for (int cp = 0; cp < 4; cp++) {
                    pfma(acc[rp][cp][0], rr[rp], cn[cp]);
                    pfma(acc[rp][cp][1], rr[rp], cs[cp]);
                }
        }
        __syncthreads();
    }

    // unscramble diagonals -> v[r][c]
    float v[8][8];
#pragma unroll
    for (int rp = 0; rp < 4; rp++)
#pragma unroll
        for (int cp = 0; cp < 4; cp++) {
            v[2 * rp][2 * cp]         = lo32(acc[rp][cp][0]);
            v[2 * rp + 1][2 * cp + 1] = hi32(acc[rp][cp][0]);
            v[2 * rp][2 * cp + 1]     = lo32(acc[rp][cp][1]);
            v[2 * rp + 1][2 * cp]     = hi32(acc[rp][cp][1]);
        }

    if (DO_GELU) {
        float b8[8];
#pragma unroll
        for (int q = 0; q < 8; q++) b8[q] = bias[c0 + q];
#pragma unroll
        for (int r = 0; r < 8; r++) {
            int m = m0 + r0 + r;
            if (m < M) {
#pragma unroll
                for (int q = 0; q < 8; q++) v[r][q] = gelu_exact(v[r][q] + b8[q]);
                float4 o0 = make_float4(v[r][0], v[r][1], v[r][2], v[r][3]);
                float4 o1 = make_float4(v[r][4], v[r][5], v[r][6], v[r][7]);
                *(float4*)&C[(size_t)m * Hq + c0] = o0;
                *(float4*)&C[(size_t)m * Hq + c0 + 4] = o1;
            }
        }
    }

    if (OUT_BF16) {
#pragma unroll
        for (int r = 0; r < 8; r++) {
            int m = m0 + r0 + r;
            if (m < M) {
                uint4 o;
                o.x = bfpack(v[r][0], v[r][1]);
                o.y = bfpack(v[r][2], v[r][3]);
                o.z = bfpack(v[r][4], v[r][5]);
                o.w = bfpack(v[r][6], v[r][7]);
                *(uint4*)&g_hpb[(size_t)m * (Hq / 2) + tx * 4] = o;
            }
        }
    }

    if (DO_ATTN) {
        // each thread's 8 cols lie within one head (head = tx>>2)
        float as8[8], ad8[8];
#pragma unroll
        for (int q = 0; q < 8; q++) { as8[q] = a_s[c0 + q]; ad8[q] = a_d[c0 + q]; }
        int head = tx >> 2;
#pragma unroll
        for (int r = 0; r < 8; r++) {
            float ps = 0.f, pd = 0.f;
#pragma unroll
            for (int q = 0; q < 8; q++) { ps += v[r][q] * as8[q]; pd += v[r][q] * ad8[q]; }
            ps += __shfl_xor_sync(0xffffffffu, ps, 1);
            pd += __shfl_xor_sync(0xffffffffu, pd, 1);
            ps += __shfl_xor_sync(0xffffffffu, ps, 2);
            pd += __shfl_xor_sync(0xffffffffu, pd, 2);
            int m = m0 + r0 + r;
            if ((lane & 3) == 0 && m < M) {
                g_alS[m * 4 + head] = ps;
                g_alD[m * 4 + head] = pd;
            }
        }
    }
}

// ================= CSR build =================
__global__ void zero_cnt()
{
    int i = blockIdx.x * blockDim.x + threadIdx.x;
    if (i < Nn) g_cnt_i[i] = 0;
}

__global__ void hist_dst(const int* __restrict__ ei)
{
    int e = blockIdx.x * blockDim.x + threadIdx.x;
    if (e >= ETOT) return;
    int d = (e < Ee) ? ei[Ee + e] : (e - Ee);
    atomicAdd(&g_cnt_i[d], 1);
}

__global__ void scan1()
{
    __shared__ int s[256];
    int i = blockIdx.x * 256 + threadIdx.x;
    int v = (i < Nn) ? g_cnt_i[i] : 0;
    s[threadIdx.x] = v;
    __syncthreads();
#pragma unroll
    for (int o = 1; o < 256; o <<= 1) {
        int t = (threadIdx.x >= o) ? s[threadIdx.x - o] : 0;
        __syncthreads();
        s[threadIdx.x] += t;
        __syncthreads();
    }
    if (i < Nn) g_rowptr[i] = s[threadIdx.x] - v;
    if (threadIdx.x == 255) g_blocksums[blockIdx.x] = s[255];
}

__global__ void scan2(int nblocks)
{
    __shared__ int s[512];
    int t = threadIdx.x;
    int v = (t < nblocks) ? g_blocksums[t] : 0;
    s[t] = v;
    __syncthreads();
#pragma unroll
    for (int o = 1; o < 512; o <<= 1) {
        int u = (t >= o) ? s[t - o] : 0;
        __syncthreads();
        s[t] += u;
        __syncthreads();
    }
    if (t < nblocks) g_blocksums[t] = s[t] - v;
}

__global__ void scan3()
{
    int i = blockIdx.x * 256 + threadIdx.x;
    if (i < Nn) {
        int r = g_rowptr[i] + g_blocksums[blockIdx.x];
        g_rowptr[i] = r;
        g_cursor[i] = r;
    }
    if (i == 0) g_rowptr[Nn] = ETOT;
}

__global__ void csr_fill(const int* __restrict__ ei)
{
    int e = blockIdx.x * blockDim.x + threadIdx.x;
    if (e >= ETOT) return;
    int s, d;
    if (e < Ee) { s = ei[e]; d = ei[Ee + e]; } else { s = d = e - Ee; }
    int pos = atomicAdd(&g_cursor[d], 1);
    g_csr_src[pos] = s;
}

// == single-pass GAT aggregation (num/den together) + bias + residual + LN ==
__global__ void gat_agg_ln(const float* __restrict__ bg, const float* __restrict__ ga,
                           const float* __restrict__ be)
{
    int n = blockIdx.x * 8 + (threadIdx.x >> 5);
    if (n >= Nn) return;
    int lane = threadIdx.x & 31;
    int hd = lane >> 3;
    int start = g_rowptr[n];
    int end   = g_rowptr[n + 1];

    float adh = g_alD[n * 4 + hd];

    float a0 = 0.f, a1 = 0.f, a2 = 0.f, a3 = 0.f, den = 0.f;
    int i = start;
    for (; i + 1 < end; i += 2) {
        int s0 = g_csr_src[i];
        int s1 = g_csr_src[i + 1];
        float la = g_alS[s0 * 4 + hd] + adh;
        float lb = g_alS[s1 * 4 + hd] + adh;
        la = (la > 0.f) ? la : 0.2f * la;
        lb = (lb > 0.f) ? lb : 0.2f * lb;
        float e0 = __expf(la);
        float e1 = __expf(lb);
        den += e0 + e1;
        uint2 p0 = *(const uint2*)&g_hpb[(size_t)s0 * (Hq / 2) + lane * 2];
        uint2 p1 = *(const uint2*)&g_hpb[(size_t)s1 * (Hq / 2) + lane * 2];
        a0 += e0 * __uint_as_float(p0.x << 16) + e1 * __uint_as_float(p1.x << 16);
        a1 += e0 * __uint_as_float(p0.x & 0xffff0000u) + e1 * __uint_as_float(p1.x & 0xffff0000u);
        a2 += e0 * __uint_as_float(p0.y << 16) + e1 * __uint_as_float(p1.y << 16);
        a3 += e0 * __uint_as_float(p0.y & 0xffff0000u) + e1 * __uint_as_float(p1.y & 0xffff0000u);
    }
    if (i < end) {
        int s0 = g_csr_src[i];
        float la = g_alS[s0 * 4 + hd] + adh;
        la = (la > 0.f) ? la : 0.2f * la;
        float e0 = __expf(la);
        den += e0;
        uint2 p0 = *(const uint2*)&g_hpb[(size_t)s0 * (Hq / 2) + lane * 2];
        a0 += e0 * __uint_as_float(p0.x << 16);
        a1 += e0 * __uint_as_float(p0.x & 0xffff0000u);
        a2 += e0 * __uint_as_float(p0.y << 16);
        a3 += e0 * __uint_as_float(p0.y & 0xffff0000u);
    }

    float dinv = 1.0f / (den + 1e-16f);
    a0 *= dinv; a1 *= dinv; a2 *= dinv; a3 *= dinv;

    // epilogue: bias + residual + layernorm
    size_t base = (size_t)n * Hq + lane * 4;
    float4 hv = *(const float4*)&g_h[base];
    float4 b4 = *(const float4*)&bg[lane * 4];
    float v0 = a0 + b4.x + hv.x;
    float v1 = a1 + b4.y + hv.y;
    float v2 = a2 + b4.z + hv.z;
    float v3 = a3 + b4.w + hv.w;

    float s = v0 + v1 + v2 + v3;
#pragma unroll
    for (int o = 16; o; o >>= 1) s += __shfl_xor_sync(0xffffffffu, s, o);
    float mu = s * (1.0f / 128.0f);
    float d0 = v0 - mu, d1 = v1 - mu, d2 = v2 - mu, d3 = v3 - mu;
    float q = d0 * d0 + d1 * d1 + d2 * d2 + d3 * d3;
#pragma unroll
    for (int o = 16; o; o >>= 1) q += __shfl_xor_sync(0xffffffffu, q, o);
    float rs = rsqrtf(q * (1.0f / 128.0f) + 1e-5f);

    float4 g4 = *(const float4*)&ga[lane * 4];
    float4 e4 = *(const float4*)&be[lane * 4];
    float4 outv;
    outv.x = d0 * rs * g4.x + e4.x;
    outv.y = d1 * rs * g4.y + e4.y;
    outv.z = d2 * rs * g4.z + e4.z;
    outv.w = d3 * rs * g4.w + e4.w;
    *(float4*)&g_h[base] = outv;
}

// ---------------- pooling ----------------
__global__ void pool_clear()
{
    int idx = blockIdx.x * blockDim.x + threadIdx.x;
    if (idx < Gq * Hq) { g_psum[idx] = 0.f; g_pmax[idx] = -INFINITY; }
    if (idx < Gq) g_gcnt[idx] = 0.f;
}

__global__ void pool_chunk(const int* __restrict__ n2g)
{
    __shared__ int sg[256];
    int d  = threadIdx.x;
    int n0 = blockIdx.x * 256;
    int n1 = n0 + 256; if (n1 > Nn) n1 = Nn;
    int cn = n1 - n0;
    for (int i = d; i < cn; i += 128) sg[i] = n2g[n0 + i];
    __syncthreads();

    int   curg = sg[0];
    float sum = 0.f, mx = -INFINITY;
    int   cnt = 0;
    for (int j = 0; j < cn; j++) {
        int g = sg[j];
        if (g != curg) {
            atomicAdd(&g_psum[curg * Hq + d], sum);
            atomicMaxFloat(&g_pmax[curg * Hq + d], mx);
            if (d == 0) atomicAdd(&g_gcnt[curg], (float)cnt);
            sum = 0.f; mx = -INFINITY; cnt = 0; curg = g;
        }
        float v = g_h[(size_t)(n0 + j) * Hq + d];
        sum += v; mx = fmaxf(mx, v); cnt++;
    }
    atomicAdd(&g_psum[curg * Hq + d], sum);
    atomicMaxFloat(&g_pmax[curg * Hq + d], mx);
    if (d == 0) atomicAdd(&g_gcnt[curg], (float)cnt);
}

// ---------------- final MLP head ----------------
__global__ void final_mlp(const float* __restrict__ Wq1, const float* __restrict__ bq1,
                          const float* __restrict__ gq, const float* __restrict__ beq,
                          const float* __restrict__ Wq2, const float* __restrict__ bq2,
                          float* __restrict__ out)
{
    int g = blockIdx.x;
    int tid = threadIdx.x;   // 256
    __shared__ float emb[2 * Hq];
    __shared__ float p[Hq];
    __shared__ float stats[2];

    if (tid < Hq) emb[tid] = g_psum[g * Hq + tid] / fmaxf(g_gcnt[g], 1.0f);
    else          emb[tid] = g_pmax[g * Hq + (tid - Hq)];
    __syncthreads();

    if (tid < Hq) {
        float t = bq1[tid];
        for (int k = 0; k < 2 * Hq; k++) t += emb[k] * Wq1[k * Hq + tid];
        p[tid] = t;
    }
    __syncthreads();

    if (tid == 0) {
        float s = 0.f;
        for (int j = 0; j < Hq; j++) s += p[j];
        float mu = s * (1.0f / 128.0f);
        float v = 0.f;
        for (int j = 0; j < Hq; j++) { float dd = p[j] - mu; v += dd * dd; }
        stats[0] = mu;
        stats[1] = rsqrtf(v * (1.0f / 128.0f) + 1e-5f);
    }
    __syncthreads();

    if (tid < Hq) {
        float y = (p[tid] - stats[0]) * stats[1] * gq[tid] + beq[tid];
        p[tid] = gelu_exact(y);
    }
    __syncthreads();

    float o = bq2[tid];
    for (int k = 0; k < Hq; k++) o += p[k] * Wq2[k * FOUTq + tid];
    out[g * FOUTq + tid] = o;
}

// ---------------- launch ----------------
extern "C" void kernel_launch(void* const* d_in, const int* in_sizes, int n_in,
                              void* d_out, int out_size)
{
    const float* x   = (const float*)d_in[0];
    const int*   ei  = (const int*)d_in[1];
    const int*   n2g = (const int*)d_in[2];
    const float* Wp  = (const float*)d_in[3];
    const float* bp  = (const float*)d_in[4];
    const float* Wq1 = (const float*)d_in[5];
    const float* bq1 = (const float*)d_in[6];
    const float* gq  = (const float*)d_in[7];
    const float* beq = (const float*)d_in[8];
    const float* Wq2 = (const float*)d_in[9];
    const float* bq2 = (const float*)d_in[10];
    float* out = (float*)d_out;

    float* ph = nullptr;
    cudaGetSymbolAddress((void**)&ph, g_h);

    static cudaStream_t s2 = nullptr;
    static cudaEvent_t evA = nullptr, evB = nullptr;
    if (s2 == nullptr) {
        cudaStreamCreateWithFlags(&s2, cudaStreamNonBlocking);
        cudaEventCreateWithFlags(&evA, cudaEventDisableTiming);
        cudaEventCreateWithFlags(&evB, cudaEventDisableTiming);
    }

    const int NB_GEMM = (Nn + 127) / 128;
    const int NB_N    = (Nn + 255) / 256;
    const int NB_E    = (ETOT + 255) / 256;
    const int NB_AGG  = (Nn + 7) / 8;
    const int NB_POOL = (Nn + 255) / 256;

    // ---- fork CSR build onto side stream ----
    cudaEventRecord(evA, 0);
    cudaStreamWaitEvent(s2, evA, 0);
    zero_cnt<<<NB_N, 256, 0, s2>>>();
    hist_dst<<<NB_E, 256, 0, s2>>>(ei);
    scan1<<<NB_N, 256, 0, s2>>>();
    scan2<<<1, 512, 0, s2>>>(NB_N);
    scan3<<<NB_N, 256, 0, s2>>>();
    csr_fill<<<NB_E, 256, 0, s2>>>(ei);
    cudaEventRecord(evB, s2);

    // ---- projection: h = gelu(x @ Wp + bp), fp32 out ----
    gemm128T<DINq, true, false, false><<<NB_GEMM, 256>>>(x, Wp, bp, nullptr, nullptr, ph, Nn);

    // ---- layer 0 GEMM: bf16 hp + fused attn logits ----
    gemm128T<Hq, false, true, true><<<NB_GEMM, 256>>>(
        ph, (const float*)d_in[11], nullptr,
        (const float*)d_in[12], (const float*)d_in[13], nullptr, Nn);

    cudaStreamWaitEvent(0, evB, 0);   // join: aggregation needs CSR

    gat_agg_ln<<<NB_AGG, 256>>>((const float*)d_in[14], (const float*)d_in[15],
                                (const float*)d_in[16]);

    // ---- layer 1 ----
    gemm128T<Hq, false, true, true><<<NB_GEMM, 256>>>(
        ph, (const float*)d_in[17], nullptr,
        (const float*)d_in[18], (const float*)d_in[19], nullptr, Nn);
    gat_agg_ln<<<NB_AGG, 256>>>((const float*)d_in[20], (const float*)d_in[21],
                                (const float*)d_in[22]);

    pool_clear<<<(Gq * Hq + 255) / 256, 256>>>();
    pool_chunk<<<NB_POOL, 128>>>(n2g);
    final_mlp<<<Gq, 256>>>(Wq1, bq1, gq, beq, Wq2, bq2, out);
}